// round 5
// baseline (speedup 1.0000x reference)
#include <cuda_runtime.h>

#define BATCH 16
#define SEQ   1024
#define HID   768
#define NH    8
#define HD    96
#define NJS   16         // j-chunks of 64 rows (flash-style split softmax)
#define JC    64         // rows per chunk

// 1/sqrt(96)
#define INV_SQRT_D 0.10206207261596577f

// ---------------- scratch (device globals: no allocations allowed) ----------
__device__ __align__(16) float g_u[BATCH * NH * HID];          // q0 @ Wk^T vectors
__device__            float g_s0[BATCH * NH];                  // q0 . bk per (b,h)
__device__            float g_m[NJS * BATCH * NH];             // chunk max
__device__            float g_l[NJS * BATCH * NH];             // chunk exp-sum
__device__ __align__(16) float g_wpart[NJS * BATCH * NH * HID];// 6 MB partials

// ---------------------------------------------------------------------------
// Kernel 1: per (b,h): q0[96] = hidden[b,0,:] @ Wq[:,h*96:+96] + bq;
// u[b,h,c] = sum_d q0[d] * Wk[c, h*96+d];  s0 = q0 . bk_head.
// grid (NH, BATCH), block 256
// ---------------------------------------------------------------------------
__global__ __launch_bounds__(256) void k_qk(
                     const float* __restrict__ hid,
                     const float* __restrict__ Wq, const float* __restrict__ bq,
                     const float* __restrict__ Wk, const float* __restrict__ bk) {
    int h = blockIdx.x, b = blockIdx.y;
    int tid = threadIdx.x;

    __shared__ float h0s[HID];
    __shared__ float q0s[HD];
    __shared__ float s0red[HD];

    for (int i = tid; i < HID; i += 256)
        h0s[i] = hid[(size_t)b * SEQ * HID + i];     // row (b, 0)
    __syncthreads();

    if (tid < HD) {
        int d = tid;
        float acc = bq[h * HD + d];
        const float* wq = Wq + h * HD + d;           // column h*96+d, stride HID
        #pragma unroll 8
        for (int c = 0; c < HID; c++)
            acc += h0s[c] * wq[c * HID];
        q0s[d] = acc;
        s0red[d] = acc * bk[h * HD + d];
    }
    __syncthreads();

    if (tid == 0) {
        float s = 0.f;
        #pragma unroll 8
        for (int d = 0; d < HD; d++) s += s0red[d];
        g_s0[b * NH + h] = s;
    }

    for (int c = tid; c < HID; c += 256) {
        const float* wk = Wk + (size_t)c * HID + h * HD;
        float acc = 0.f;
        #pragma unroll
        for (int d = 0; d < HD; d++) acc += q0s[d] * wk[d];
        g_u[((size_t)b * NH + h) * HID + c] = acc;
    }
}

// ---------------------------------------------------------------------------
// Kernel 2 (fused): per (chunk jc of 64 rows, b):
//   pass 1: scores[j,h] = (hidden[b,j,:] . u[b,h,:] + s0) / sqrt(96) + mask
//   local softmax: m[h] = max_j, p[j,h] = exp(score - m), l[h] = sum_j p
//   pass 2: wpart[h,c] = sum_j p[j,h] * hidden[b,j,c]   (rows L1-resident)
// grid (NJS, BATCH), block 256 (8 warps).
// ---------------------------------------------------------------------------
__global__ __launch_bounds__(256) void k_attn(
                         const float* __restrict__ hid,
                         const float* __restrict__ mask) {
    int jc = blockIdx.x, b = blockIdx.y;
    int tid = threadIdx.x;
    int warp = tid >> 5, lane = tid & 31;

    __shared__ __align__(16) float4 u4[NH][HID / 4];   // 24 KB
    __shared__ float s0s[NH];
    __shared__ __align__(16) float sc[JC][NH + 1];     // stride 9: conflict-free cols
    __shared__ __align__(16) float p_s[JC][NH];        // exp weights, float4 rows
    __shared__ float m_s[NH], l_s[NH];

    const float4* ub = (const float4*)(g_u + (size_t)b * NH * HID);
    for (int i = tid; i < NH * HID / 4; i += 256)
        (&u4[0][0])[i] = ub[i];
    if (tid < NH) s0s[tid] = g_s0[b * NH + tid];
    __syncthreads();

    // ---- pass 1: scores for 64 rows, all 8 heads ----
    #pragma unroll 2
    for (int i = 0; i < 8; i++) {                    // 8 iters x 8 warps = 64 rows
        int jl = i * 8 + warp;
        int j  = jc * JC + jl;
        const float4* hrow = (const float4*)(hid + ((size_t)b * SEQ + j) * HID);

        float acc[NH];
        #pragma unroll
        for (int h = 0; h < NH; h++) acc[h] = 0.f;

        #pragma unroll
        for (int k = 0; k < HID / 128; k++) {        // 6 float4 per lane
            float4 x = hrow[lane + 32 * k];
            #pragma unroll
            for (int h = 0; h < NH; h++) {
                float4 uu = u4[h][lane + 32 * k];
                acc[h] += x.x * uu.x + x.y * uu.y + x.z * uu.z + x.w * uu.w;
            }
        }
        #pragma unroll
        for (int h = 0; h < NH; h++) {
            #pragma unroll
            for (int off = 16; off > 0; off >>= 1)
                acc[h] += __shfl_xor_sync(0xffffffff, acc[h], off);
        }
        if (lane == 0) {
            float am = (1.0f - mask[b * SEQ + j]) * -10000.0f;
            #pragma unroll
            for (int h = 0; h < NH; h++)
                sc[jl][h] = (acc[h] + s0s[h]) * INV_SQRT_D + am;
        }
    }
    __syncthreads();

    // ---- local softmax stats: warp h owns head h ----
    {
        int h = warp;
        float v0 = sc[lane][h], v1 = sc[lane + 32][h];
        float m = fmaxf(v0, v1);
        #pragma unroll
        for (int off = 16; off > 0; off >>= 1)
            m = fmaxf(m, __shfl_xor_sync(0xffffffff, m, off));
        float e0 = __expf(v0 - m), e1 = __expf(v1 - m);
        float l = e0 + e1;
        #pragma unroll
        for (int off = 16; off > 0; off >>= 1)
            l += __shfl_xor_sync(0xffffffff, l, off);
        p_s[lane][h] = e0;
        p_s[lane + 32][h] = e1;
        if (lane == 0) { m_s[h] = m; l_s[h] = l; }
    }
    __syncthreads();

    // ---- pass 2: exp-weighted hidden sum (rows hot in L1 from pass 1) ----
    if (tid < HID / 4) {                   // warps 0..5: 192 active threads
        float acc[NH][4];
        #pragma unroll
        for (int h = 0; h < NH; h++)
            #pragma unroll
            for (int q = 0; q < 4; q++) acc[h][q] = 0.f;

        const float4* hb = (const float4*)(hid + ((size_t)b * SEQ + jc * JC) * HID);
        #pragma unroll 4
        for (int j = 0; j < JC; j++) {
            float4 x = hb[j * (HID / 4) + tid];
            const float4* pj = (const float4*)p_s[j];
            float4 pa = pj[0], pb2 = pj[1];
            float ph[NH] = {pa.x, pa.y, pa.z, pa.w, pb2.x, pb2.y, pb2.z, pb2.w};
            #pragma unroll
            for (int h = 0; h < NH; h++) {
                acc[h][0] += ph[h] * x.x; acc[h][1] += ph[h] * x.y;
                acc[h][2] += ph[h] * x.z; acc[h][3] += ph[h] * x.w;
            }
        }
        float* wp = g_wpart + (((size_t)jc * BATCH + b) * NH) * HID;
        #pragma unroll
        for (int h = 0; h < NH; h++)
            ((float4*)(wp + h * HID))[tid] =
                make_float4(acc[h][0], acc[h][1], acc[h][2], acc[h][3]);
    } else if (warp == 7) {                // threads 224..255 export stats
        if (lane < NH)
            g_m[((size_t)jc * BATCH + b) * NH + lane] = m_s[lane];
        else if (lane < 2 * NH)
            g_l[((size_t)jc * BATCH + b) * NH + (lane - NH)] = l_s[lane - NH];
    }
}

// ---------------------------------------------------------------------------
// Kernel 3: combine chunks (flash rescale), Wv projection, Wo + relu.
// grid (BATCH), block 256.
// ---------------------------------------------------------------------------
__global__ __launch_bounds__(256) void k_final(
                        const float* __restrict__ Wv, const float* __restrict__ bv,
                        const float* __restrict__ Wo, const float* __restrict__ bo,
                        float* __restrict__ out) {
    int b = blockIdx.x, tid = threadIdx.x;

    __shared__ float coefn[NJS][NH];       // exp(m_js - m_glob) / l_glob
    __shared__ float w_s[NH * HID];        // 24 KB
    __shared__ float ctx_s[HID];

    if (tid < NH) {
        int h = tid;
        float m = -1e30f;
        float mj[NJS];
        #pragma unroll
        for (int js = 0; js < NJS; js++) {
            mj[js] = g_m[((size_t)js * BATCH + b) * NH + h];
            m = fmaxf(m, mj[js]);
        }
        float l = 0.f;
        float cf[NJS];
        #pragma unroll
        for (int js = 0; js < NJS; js++) {
            cf[js] = __expf(mj[js] - m);
            l += cf[js] * g_l[((size_t)js * BATCH + b) * NH + h];
        }
        float inv = 1.0f / l;
        #pragma unroll
        for (int js = 0; js < NJS; js++)
            coefn[js][h] = cf[js] * inv;
    }
    __syncthreads();

    // w[h,c] = sum_js coefn[js][h] * wpart[js,b,h,c]
    for (int idx = tid; idx < NH * HID; idx += 256) {
        int h = idx / HID;
        float s = 0.f;
        #pragma unroll
        for (int js = 0; js < NJS; js++)
            s += coefn[js][h] *
                 g_wpart[(((size_t)js * BATCH + b) * NH) * HID + idx];
        w_s[idx] = s;
    }
    __syncthreads();

    // ctx[o] = w[h(o),:] . Wv[:,o] + bv[o]
    #pragma unroll
    for (int r = 0; r < 3; r++) {
        int o = tid + 256 * r;
        int h = o / HD;
        const float* wrow = w_s + h * HID;
        float acc = bv[o];
        #pragma unroll 8
        for (int c = 0; c < HID; c++)
            acc += wrow[c] * Wv[(size_t)c * HID + o];
        ctx_s[o] = acc;
    }
    __syncthreads();

    int warp = tid >> 5, lane = tid & 31;
    if (warp < 4) {
        int f = warp;
        float acc = 0.f;
        #pragma unroll
        for (int k = 0; k < HID / 32; k++) {
            int o = lane + 32 * k;
            acc += ctx_s[o] * Wo[o * 4 + f];
        }
        #pragma unroll
        for (int off = 16; off > 0; off >>= 1)
            acc += __shfl_xor_sync(0xffffffff, acc, off);
        if (lane == 0)
            out[b * 4 + f] = fmaxf(acc + bo[f], 0.f);
    }
}

// ---------------------------------------------------------------------------
extern "C" void kernel_launch(void* const* d_in, const int* in_sizes, int n_in,
                              void* d_out, int out_size) {
    const float* hid  = (const float*)d_in[0];
    const float* mask = (const float*)d_in[1];
    const float* Wq   = (const float*)d_in[2];
    const float* bq   = (const float*)d_in[3];
    const float* Wk   = (const float*)d_in[4];
    const float* bk   = (const float*)d_in[5];
    const float* Wv   = (const float*)d_in[6];
    const float* bv   = (const float*)d_in[7];
    const float* Wo   = (const float*)d_in[8];
    const float* bo   = (const float*)d_in[9];
    float* out = (float*)d_out;

    k_qk   <<<dim3(NH, BATCH),   256>>>(hid, Wq, bq, Wk, bk);
    k_attn <<<dim3(NJS, BATCH),  256>>>(hid, mask);
    k_final<<<BATCH,             256>>>(Wv, bv, Wo, bo, out);
}

// round 11
// speedup vs baseline: 1.8055x; 1.8055x over previous
#include <cuda_runtime.h>

#define BATCH 16
#define SEQ   1024
#define HID   768
#define NH    8
#define HD    96
#define NJS   16         // j-chunks of 64 rows (flash-style split softmax)
#define JC    64         // rows per chunk
#define CS    8          // c-chunks for q0 partials

#define INV_SQRT_D 0.10206207261596577f

// ---------------- scratch (device globals: no allocations allowed) ----------
__device__ __align__(16) float g_q0p[CS * BATCH * HID];        // q0 partials
__device__ __align__(16) float g_q0[BATCH * HID];              // q0 full
__device__            float g_s0[BATCH * NH];                  // q0 . bk per (b,h)
__device__ __align__(16) float g_u[BATCH * NH * HID];          // q0 @ Wk^T vectors
__device__            float g_m[NJS * BATCH * NH];             // chunk max
__device__            float g_l[NJS * BATCH * NH];             // chunk exp-sum
__device__ __align__(16) float g_wpart[NJS * BATCH * NH * HID];// 6 MB partials
__device__ __align__(16) float g_ctx[BATCH * HID];             // attention context

// ---------------------------------------------------------------------------
// k_q0p: partial q0[b,o] over c-chunk cs (rank-1 updates, fully coalesced).
// grid (CS, BATCH), block 192 (each thread owns one float4 of the 768 outputs)
// ---------------------------------------------------------------------------
__global__ __launch_bounds__(192) void k_q0p(const float* __restrict__ hid,
                                             const float* __restrict__ Wq) {
    int cs = blockIdx.x, b = blockIdx.y, tid = threadIdx.x;

    __shared__ float h0s[HD];
    if (tid < HD) h0s[tid] = hid[(size_t)b * SEQ * HID + cs * HD + tid];
    __syncthreads();

    const float4* Wq4 = (const float4*)(Wq + (size_t)cs * HD * HID);
    float4 acc = make_float4(0.f, 0.f, 0.f, 0.f);
    #pragma unroll 8
    for (int c = 0; c < HD; c++) {
        float hv = h0s[c];
        float4 w = Wq4[c * (HID / 4) + tid];
        acc.x += hv * w.x; acc.y += hv * w.y;
        acc.z += hv * w.z; acc.w += hv * w.w;
    }
    ((float4*)(g_q0p + ((size_t)cs * BATCH + b) * HID))[tid] = acc;
}

// ---------------------------------------------------------------------------
// k_q0r: q0[b,:] = bq + sum_cs partials; s0[b,h] = q0_slice . bk_slice.
// grid (BATCH), block 256.
// ---------------------------------------------------------------------------
__global__ __launch_bounds__(256) void k_q0r(const float* __restrict__ bq,
                                             const float* __restrict__ bk) {
    int b = blockIdx.x, tid = threadIdx.x;
    int warp = tid >> 5, lane = tid & 31;

    __shared__ float q0s[HID];

    if (tid < HID / 4) {
        float4 a = ((const float4*)bq)[tid];
        #pragma unroll
        for (int cs = 0; cs < CS; cs++) {
            float4 p = ((const float4*)(g_q0p + ((size_t)cs * BATCH + b) * HID))[tid];
            a.x += p.x; a.y += p.y; a.z += p.z; a.w += p.w;
        }
        ((float4*)q0s)[tid] = a;
        ((float4*)(g_q0 + (size_t)b * HID))[tid] = a;
    }
    __syncthreads();

    // warp h computes s0[b,h]
    int h = warp;
    float s = 0.f;
    #pragma unroll
    for (int r = 0; r < 3; r++) {
        int d = lane + 32 * r;
        s += q0s[h * HD + d] * bk[h * HD + d];
    }
    #pragma unroll
    for (int off = 16; off > 0; off >>= 1)
        s += __shfl_xor_sync(0xffffffff, s, off);
    if (lane == 0) g_s0[b * NH + h] = s;
}

// ---------------------------------------------------------------------------
// k_u: u[b,h,c] = sum_d q0[b,h*96+d] * Wk[c,h*96+d].
// grid (NH, 24 c-chunks of 32 rows), block 256. Wk tile staged in smem
// (coalesced load; 400B row stride is LDS.128 quarter-conflict-free);
// outputs for all 16 b amortize each tile read.
// ---------------------------------------------------------------------------
__global__ __launch_bounds__(256) void k_u(const float* __restrict__ Wk) {
    int h = blockIdx.x, cc = blockIdx.y, tid = threadIdx.x;

    __shared__ __align__(16) float q0t[BATCH][HD];   // 6 KB (reads broadcast)
    __shared__ __align__(16) float wk[32][100];      // 12.5 KB padded

    for (int idx = tid; idx < BATCH * HD; idx += 256) {
        int b = idx / HD, d = idx % HD;
        q0t[b][d] = g_q0[(size_t)b * HID + h * HD + d];
    }
    for (int idx = tid; idx < 32 * HD; idx += 256) {
        int row = idx / HD, col = idx % HD;
        wk[row][col] = Wk[(size_t)(cc * 32 + row) * HID + h * HD + col];
    }
    __syncthreads();

    int c_local = tid & 31;
    int b0 = (tid >> 5) * 2;                         // 2 b's per thread
    const float4* wrow = (const float4*)wk[c_local]; // 24 float4, conflict-free
    const float4* qa = (const float4*)q0t[b0];
    const float4* qb = (const float4*)q0t[b0 + 1];

    float acc0 = 0.f, acc1 = 0.f;
    #pragma unroll
    for (int dq = 0; dq < HD / 4; dq++) {
        float4 w = wrow[dq];
        float4 a = qa[dq];
        float4 bb = qb[dq];
        acc0 += w.x * a.x + w.y * a.y + w.z * a.z + w.w * a.w;
        acc1 += w.x * bb.x + w.y * bb.y + w.z * bb.z + w.w * bb.w;
    }
    int c = cc * 32 + c_local;
    g_u[((size_t)b0 * NH + h) * HID + c] = acc0;
    g_u[((size_t)(b0 + 1) * NH + h) * HID + c] = acc1;
}

// ---------------------------------------------------------------------------
// k_attn (fused): per (chunk of 64 rows, b): scores (4-row register blocked),
// local softmax, exp-weighted hidden sum. grid (NJS, BATCH), block 256.
// ---------------------------------------------------------------------------
__global__ __launch_bounds__(256, 2) void k_attn(
                         const float* __restrict__ hid,
                         const float* __restrict__ mask) {
    int jc = blockIdx.x, b = blockIdx.y;
    int tid = threadIdx.x;
    int warp = tid >> 5, lane = tid & 31;

    __shared__ __align__(16) float4 u4[NH][HID / 4];   // 24 KB
    __shared__ float s0s[NH];
    __shared__ __align__(16) float sc[JC][NH + 1];     // stride 9: conflict-free cols
    __shared__ __align__(16) float p_s[JC][NH];        // exp weights, float4 rows
    __shared__ float m_s[NH], l_s[NH];

    const float4* ub = (const float4*)(g_u + (size_t)b * NH * HID);
    for (int i = tid; i < NH * HID / 4; i += 256)
        (&u4[0][0])[i] = ub[i];
    if (tid < NH) s0s[tid] = g_s0[b * NH + tid];
    __syncthreads();

    // ---- pass 1: scores, 4 rows per warp-iteration (u LDS amortized 4x) ----
    #pragma unroll
    for (int i = 0; i < 2; i++) {
        int jl0 = i * 32 + warp * 4;
        int j0  = jc * JC + jl0;
        const float4* r0 = (const float4*)(hid + ((size_t)b * SEQ + j0 + 0) * HID);
        const float4* r1 = (const float4*)(hid + ((size_t)b * SEQ + j0 + 1) * HID);
        const float4* r2 = (const float4*)(hid + ((size_t)b * SEQ + j0 + 2) * HID);
        const float4* r3 = (const float4*)(hid + ((size_t)b * SEQ + j0 + 3) * HID);

        float acc[4][NH];
        #pragma unroll
        for (int r = 0; r < 4; r++)
            #pragma unroll
            for (int h = 0; h < NH; h++) acc[r][h] = 0.f;

        #pragma unroll
        for (int k = 0; k < HID / 128; k++) {
            float4 x0 = r0[lane + 32 * k];
            float4 x1 = r1[lane + 32 * k];
            float4 x2 = r2[lane + 32 * k];
            float4 x3 = r3[lane + 32 * k];
            #pragma unroll
            for (int h = 0; h < NH; h++) {
                float4 uu = u4[h][lane + 32 * k];
                acc[0][h] += x0.x * uu.x + x0.y * uu.y + x0.z * uu.z + x0.w * uu.w;
                acc[1][h] += x1.x * uu.x + x1.y * uu.y + x1.z * uu.z + x1.w * uu.w;
                acc[2][h] += x2.x * uu.x + x2.y * uu.y + x2.z * uu.z + x2.w * uu.w;
                acc[3][h] += x3.x * uu.x + x3.y * uu.y + x3.z * uu.z + x3.w * uu.w;
            }
        }
        #pragma unroll
        for (int r = 0; r < 4; r++)
            #pragma unroll
            for (int h = 0; h < NH; h++)
                #pragma unroll
                for (int off = 16; off > 0; off >>= 1)
                    acc[r][h] += __shfl_xor_sync(0xffffffff, acc[r][h], off);
        if (lane == 0) {
            #pragma unroll
            for (int r = 0; r < 4; r++) {
                float am = (1.0f - mask[b * SEQ + j0 + r]) * -10000.0f;
                #pragma unroll
                for (int h = 0; h < NH; h++)
                    sc[jl0 + r][h] = (acc[r][h] + s0s[h]) * INV_SQRT_D + am;
            }
        }
    }
    __syncthreads();

    // ---- local softmax stats: warp h owns head h ----
    {
        int h = warp;
        float v0 = sc[lane][h], v1 = sc[lane + 32][h];
        float m = fmaxf(v0, v1);
        #pragma unroll
        for (int off = 16; off > 0; off >>= 1)
            m = fmaxf(m, __shfl_xor_sync(0xffffffff, m, off));
        float e0 = __expf(v0 - m), e1 = __expf(v1 - m);
        float l = e0 + e1;
        #pragma unroll
        for (int off = 16; off > 0; off >>= 1)
            l += __shfl_xor_sync(0xffffffff, l, off);
        p_s[lane][h] = e0;
        p_s[lane + 32][h] = e1;
        if (lane == 0) { m_s[h] = m; l_s[h] = l; }
    }
    __syncthreads();

    // ---- pass 2: exp-weighted hidden sum (rows hot in L1 from pass 1) ----
    if (tid < HID / 4) {                   // warps 0..5
        float acc[NH][4];
        #pragma unroll
        for (int h = 0; h < NH; h++)
            #pragma unroll
            for (int q = 0; q < 4; q++) acc[h][q] = 0.f;

        const float4* hb = (const float4*)(hid + ((size_t)b * SEQ + jc * JC) * HID);
        #pragma unroll 8
        for (int j = 0; j < JC; j++) {
            float4 x = hb[j * (HID / 4) + tid];
            const float4* pj = (const float4*)p_s[j];
            float4 pa = pj[0], pb2 = pj[1];
            float ph[NH] = {pa.x, pa.y, pa.z, pa.w, pb2.x, pb2.y, pb2.z, pb2.w};
            #pragma unroll
            for (int h = 0; h < NH; h++) {
                acc[h][0] += ph[h] * x.x; acc[h][1] += ph[h] * x.y;
                acc[h][2] += ph[h] * x.z; acc[h][3] += ph[h] * x.w;
            }
        }
        float* wp = g_wpart + (((size_t)jc * BATCH + b) * NH) * HID;
        #pragma unroll
        for (int h = 0; h < NH; h++)
            ((float4*)(wp + h * HID))[tid] =
                make_float4(acc[h][0], acc[h][1], acc[h][2], acc[h][3]);
    } else if (warp == 7) {
        if (lane < NH)
            g_m[((size_t)jc * BATCH + b) * NH + lane] = m_s[lane];
        else if (lane < 2 * NH)
            g_l[((size_t)jc * BATCH + b) * NH + (lane - NH)] = l_s[lane - NH];
    }
}

// ---------------------------------------------------------------------------
// k_ctx: flash combine + Wv projection for a 128-wide output chunk.
// grid (6 ochunks, BATCH), block 256. Each chunk spans exactly 2 heads.
// ---------------------------------------------------------------------------
__global__ __launch_bounds__(256) void k_ctx(
                        const float* __restrict__ Wv, const float* __restrict__ bv) {
    int oc = blockIdx.x, b = blockIdx.y, tid = threadIdx.x;
    int warp = tid >> 5, lane = tid & 31;

    int h_lo = (oc * 128) / HD;

    __shared__ float coef[2][NJS];
    __shared__ __align__(16) float w2[2 * HID];      // 6 KB
    __shared__ float ctx2[128];

    // warps 0,1: softmax-combine coefficients for h_lo, h_lo+1
    if (warp < 2) {
        int h = h_lo + warp;
        float m = (lane < NJS) ? g_m[((size_t)lane * BATCH + b) * NH + h] : -1e30f;
        float lv = (lane < NJS) ? g_l[((size_t)lane * BATCH + b) * NH + h] : 0.f;
        float mg = m;
        #pragma unroll
        for (int off = 8; off > 0; off >>= 1)
            mg = fmaxf(mg, __shfl_xor_sync(0xffffffff, mg, off));
        float cf = __expf(m - mg) * ((lane < NJS) ? 1.f : 0.f);
        float cl = cf * lv;
        #pragma unroll
        for (int off = 8; off > 0; off >>= 1)
            cl += __shfl_xor_sync(0xffffffff, cl, off);
        if (lane < NJS) coef[warp][lane] = cf / cl;
    }
    __syncthreads();

    // w2[r, c] = sum_js coef[r][js] * wpart[js, b, h_lo+r, c]
    for (int idx = tid; idx < 2 * HID; idx += 256) {
        int r = idx / HID, c = idx % HID;
        int h = h_lo + r;
        float s = 0.f;
        #pragma unroll
        for (int js = 0; js < NJS; js++)
            s += coef[r][js] *
                 g_wpart[(((size_t)js * BATCH + b) * NH + h) * HID + c];
        w2[idx] = s;
    }
    __syncthreads();

    // ctx[o] = w2[h(o),:] . Wv[:,o] + bv[o]; 2 threads per output (c-split)
    {
        int ol = tid & 127, half = tid >> 7;
        int o = oc * 128 + ol;
        int r = o / HD - h_lo;
        const float* wrow = w2 + r * HID;
        float acc = 0.f;
        #pragma unroll 8
        for (int c = half * (HID / 2); c < (half + 1) * (HID / 2); c++)
            acc += wrow[c] * Wv[(size_t)c * HID + o];
        if (half == 1) ctx2[ol] = acc;
        __syncthreads();
        if (half == 0)
            g_ctx[(size_t)b * HID + o] = acc + ctx2[ol] + bv[o];
    }
}

// ---------------------------------------------------------------------------
// k_out: out[b,f] = relu(ctx[b,:] . Wo[:,f] + bo[f]). grid (BATCH), block 128.
// ---------------------------------------------------------------------------
__global__ __launch_bounds__(128) void k_out(
                        const float* __restrict__ Wo, const float* __restrict__ bo,
                        float* __restrict__ out) {
    int b = blockIdx.x, tid = threadIdx.x;
    int warp = tid >> 5, lane = tid & 31;
    int f = warp;                                    // 4 warps, 4 outputs
    float acc = 0.f;
    #pragma unroll
    for (int k = 0; k < HID / 32; k++) {
        int o = lane + 32 * k;
        acc += g_ctx[(size_t)b * HID + o] * Wo[o * 4 + f];
    }
    #pragma unroll
    for (int off = 16; off > 0; off >>= 1)
        acc += __shfl_xor_sync(0xffffffff, acc, off);
    if (lane == 0)
        out[b * 4 + f] = fmaxf(acc + bo[f], 0.f);
}

// ---------------------------------------------------------------------------
extern "C" void kernel_launch(void* const* d_in, const int* in_sizes, int n_in,
                              void* d_out, int out_size) {
    const float* hid  = (const float*)d_in[0];
    const float* mask = (const float*)d_in[1];
    const float* Wq   = (const float*)d_in[2];
    const float* bq   = (const float*)d_in[3];
    const float* Wk   = (const float*)d_in[4];
    const float* bk   = (const float*)d_in[5];
    const float* Wv   = (const float*)d_in[6];
    const float* bv   = (const float*)d_in[7];
    const float* Wo   = (const float*)d_in[8];
    const float* bo   = (const float*)d_in[9];
    float* out = (float*)d_out;

    k_q0p <<<dim3(CS, BATCH),   192>>>(hid, Wq);
    k_q0r <<<BATCH,             256>>>(bq, bk);
    k_u   <<<dim3(NH, 24),      256>>>(Wk);
    k_attn<<<dim3(NJS, BATCH),  256>>>(hid, mask);
    k_ctx <<<dim3(6, BATCH),    256>>>(Wv, bv);
    k_out <<<BATCH,             128>>>(Wo, bo, out);
}